// round 5
// baseline (speedup 1.0000x reference)
#include <cuda_runtime.h>
#include <cstdint>

// ============================================================================
// DSPA via mma.sync tf32, warp-private G1->sigmoid->G2 (no mid-step barriers):
//   x2 = dilated conv1d(x1); softmax over batch(2) => P = sigmoid(d),
//   d[n,j] = <Q[n], K'[j]>_128,  O[n,c2] = sum_j P[n,j] V[c2,j]
//   out[0,c,n] = x1 + O[n,c];  out[1,c,n] = x1 + S1[c] - O[n,64+c]
// P stays in registers: C-fragment -> A-fragment via shfl. Q A-frags register-
// resident. K/V pair-interleaved for LDS.64 fragments, cp.async double-buffer.
// ============================================================================

#define NN 4096
#define NC 128
#define NJ 4096
#define NSPLIT 8
#define JRANGE 512
#define JSTEP 64
#define NSTEPS 8

__device__ __align__(256) float g_Kt[NJ * NC];          // K'[j][c2-permuted]
__device__ __align__(256) float g_V[NC * NJ];           // V[c2][j-permuted]
__device__ __align__(256) float g_Q[NN * NC];           // Q[n][c2-permuted]
__device__ __align__(256) float g_Op[NSPLIT * NC * NN]; // partial O [s][c2][n]
__device__ float g_S1[64];

// pair-interleave permutation within 8-groups: col c -> (c&3)*2 + (c>>2)
__device__ __forceinline__ int perm8(int c) {
    return (c & ~7) | (((c & 3) << 1) | ((c >> 2) & 1));
}
__device__ __forceinline__ float tf32r(float x) {
    uint32_t r;
    asm("cvt.rna.tf32.f32 %0, %1;" : "=r"(r) : "f"(x));
    return __uint_as_float(r);
}
__device__ __forceinline__ float sigf(float x) {
    return __fdividef(1.0f, 1.0f + __expf(-x));
}
__device__ __forceinline__ void mma8(float* d, const uint32_t* a, uint32_t b0, uint32_t b1) {
    asm volatile(
        "mma.sync.aligned.m16n8k8.row.col.f32.tf32.tf32.f32 "
        "{%0,%1,%2,%3}, {%4,%5,%6,%7}, {%8,%9}, {%0,%1,%2,%3};"
        : "+f"(d[0]), "+f"(d[1]), "+f"(d[2]), "+f"(d[3])
        : "r"(a[0]), "r"(a[1]), "r"(a[2]), "r"(a[3]), "r"(b0), "r"(b1));
}
__device__ __forceinline__ uint32_t smem_u32(const void* p) {
    uint32_t a;
    asm("{ .reg .u64 t; cvta.to.shared.u64 t, %1; cvt.u32.u64 %0, t; }" : "=r"(a) : "l"(p));
    return a;
}
#define CP_ASYNC16(dst, src) \
    asm volatile("cp.async.cg.shared.global [%0], [%1], 16;" :: "r"(dst), "l"(src))
#define CP_COMMIT() asm volatile("cp.async.commit_group;" ::: "memory")
#define CP_WAIT0()  asm volatile("cp.async.wait_group 0;" ::: "memory")

// ---------------------------------------------------------------------------
// Kernel 1: dilated conv -> K' (j rows, c2-permuted cols) and V (c2 rows,
// j-permuted cols), tf32-rounded, j>=4094 zero-padded.
// ---------------------------------------------------------------------------
#define CONV_SMEM_BYTES ((64 * 195 + 128 * 37) * 4)
__global__ void __launch_bounds__(512) conv_kernel(const float* __restrict__ x,
                                                   const float* __restrict__ w,
                                                   const float* __restrict__ bias) {
    extern __shared__ float sm[];
    float* ws  = sm;             // [64][195]
    float* x1s = sm + 64 * 195;  // [128][37]

    const int tid = threadIdx.x;
    const int j0 = blockIdx.x * 32;

    for (int f = tid; f < 64 * 64 * 3; f += 512) {
        int co = f / 192, rem = f % 192;
        ws[co * 195 + rem] = w[f];
    }
    for (int f = tid; f < 128 * 36; f += 512) {
        int row = f / 36, p = f % 36;
        int pos = j0 - 1 + p;
        x1s[row * 37 + p] = (pos >= 0 && pos < NN) ? x[row * NN + pos] : 0.0f;
    }
    __syncthreads();

    const int c2 = tid & 127;
    const int grp = tid >> 7;
    const int bb = c2 >> 6, co = c2 & 63;
    const int base = grp * 8;
    float acc[8];
    float bv = bias[co];
#pragma unroll
    for (int jj = 0; jj < 8; jj++) acc[jj] = bv;

    for (int ci = 0; ci < 64; ci++) {
        float w0 = ws[co * 195 + ci * 3 + 0];
        float w1 = ws[co * 195 + ci * 3 + 1];
        float w2 = ws[co * 195 + ci * 3 + 2];
        const float* xr = &x1s[(bb * 64 + ci) * 37 + base];
#pragma unroll
        for (int jj = 0; jj < 8; jj++)
            acc[jj] += w0 * xr[jj] + w1 * xr[jj + 2] + w2 * xr[jj + 4];
    }

    const int c2p = perm8(c2);
#pragma unroll
    for (int jj = 0; jj < 8; jj++) {
        int j = j0 + base + jj;
        float v = (j < 4094) ? tf32r(acc[jj]) : 0.0f;
        g_V[c2 * NJ + perm8(j)] = v;            // j permuted within its 8-group
        g_Kt[j * NC + c2p] = (c2 < 64) ? v : -v; // c2 permuted
    }
}

// ---------------------------------------------------------------------------
// Kernel 2: S1[c] = sum_j V[64+c][j] (row sum; permutation irrelevant)
// ---------------------------------------------------------------------------
__global__ void __launch_bounds__(256) s1_kernel() {
    __shared__ float red[256];
    const int c = blockIdx.x;
    float s = 0.0f;
    for (int j = threadIdx.x; j < 4096; j += 256) s += g_V[(64 + c) * NJ + j];
    red[threadIdx.x] = s;
    __syncthreads();
    for (int st = 128; st > 0; st >>= 1) {
        if (threadIdx.x < st) red[threadIdx.x] += red[threadIdx.x + st];
        __syncthreads();
    }
    if (threadIdx.x == 0) g_S1[c] = red[0];   // pad rows are zero -> safe
}

// ---------------------------------------------------------------------------
// Kernel 3: transpose x [c2][n] -> g_Q [n][c2-permuted], tf32-rounded
// ---------------------------------------------------------------------------
__global__ void transpose_kernel(const float* __restrict__ x) {
    __shared__ float t[32][33];
    int n0 = blockIdx.x * 32, c0 = blockIdx.y * 32;
    int tx = threadIdx.x, ty = threadIdx.y;  // 32 x 8
#pragma unroll
    for (int k = 0; k < 4; k++)
        t[ty + 8 * k][tx] = tf32r(x[(c0 + ty + 8 * k) * NN + n0 + tx]);
    __syncthreads();
#pragma unroll
    for (int k = 0; k < 4; k++)
        g_Q[(n0 + ty + 8 * k) * NC + perm8(c0 + tx)] = t[tx][ty + 8 * k];
}

// ---------------------------------------------------------------------------
// Kernel 4: main kernel. grid 256 = 32 m-tiles(128n) x 8 j-splits(512 j).
// block 256 (8 warps). Warp = 16 rows x full width; Q A-frags in regs;
// P converted C-frag -> A-frag via shfl (never in smem).
// smem: double-buffered K [64][136] + V [128][72]  (pair-interleaved cols)
// ---------------------------------------------------------------------------
#define KS_STRIDE 136
#define VS_STRIDE 72
#define K_FLOATS (64 * KS_STRIDE)    // 8704
#define V_FLOATS (128 * VS_STRIDE)   // 9216
#define BUF_FLOATS (K_FLOATS + V_FLOATS)
#define MAIN_SMEM_BYTES (2 * BUF_FLOATS * 4)   // 143360

__global__ void __launch_bounds__(256, 1) dspa_main_kernel() {
    extern __shared__ float sm[];
    const uint32_t smb = smem_u32(sm);
    const int tid = threadIdx.x;
    const int warp = tid >> 5, lane = tid & 31;
    const int g = lane >> 2, t = lane & 3;
    const int wr = warp * 16;                    // warp's row base within tile
    const int m0 = (blockIdx.x & 31) << 7;
    const int split = blockIdx.x >> 5;
    const int jb0 = split * JRANGE;

    // ---- stage buffer 0 (K+V for step 0) via cp.async ----
    {
        const int jb = jb0;
        uint32_t kb = smb;                         // buf0 K
        uint32_t vb = smb + K_FLOATS * 4;          // buf0 V
#pragma unroll
        for (int i = 0; i < 8; i++) {
            int c = tid + 256 * i;                 // 0..2047
            int row = c >> 5, off = c & 31;        // K: 64 rows x 32 chunks
            CP_ASYNC16(kb + row * (KS_STRIDE * 4) + off * 16,
                       (const void*)&g_Kt[(jb + row) * NC + off * 4]);
        }
#pragma unroll
        for (int i = 0; i < 8; i++) {
            int c = tid + 256 * i;
            int row = c >> 4, off = c & 15;        // V: 128 rows x 16 chunks
            CP_ASYNC16(vb + row * (VS_STRIDE * 4) + off * 16,
                       (const void*)&g_V[row * NJ + jb + off * 4]);
        }
        CP_COMMIT();
    }

    // ---- Q A-fragments, register resident (pair-permuted global layout) ----
    float2 qf0[16], qf1[16];
#pragma unroll
    for (int k = 0; k < 16; k++) {
        qf0[k] = *reinterpret_cast<const float2*>(&g_Q[(m0 + wr + g) * NC + k * 8 + 2 * t]);
        qf1[k] = *reinterpret_cast<const float2*>(&g_Q[(m0 + wr + g + 8) * NC + k * 8 + 2 * t]);
    }

    float acc2[16][4];
#pragma unroll
    for (int i = 0; i < 16; i++)
#pragma unroll
        for (int k = 0; k < 4; k++) acc2[i][k] = 0.0f;

    CP_WAIT0();
    __syncthreads();

    const int s1l = (lane & 28) | (t >> 1);   // 4g + (t>>1)
    const int s2l = s1l + 2;
    const bool odd = (t & 1);

    for (int s = 0; s < NSTEPS; s++) {
        const int cur = s & 1;
        float* Ks = sm + cur * BUF_FLOATS;
        float* Vs = Ks + K_FLOATS;

        // prefetch next step's K/V into other buffer (overlaps with compute)
        if (s + 1 < NSTEPS) {
            const int jb = jb0 + (s + 1) * JSTEP;
            uint32_t kb = smb + (cur ^ 1) * (BUF_FLOATS * 4);
            uint32_t vb = kb + K_FLOATS * 4;
#pragma unroll
            for (int i = 0; i < 8; i++) {
                int c = tid + 256 * i;
                int row = c >> 5, off = c & 31;
                CP_ASYNC16(kb + row * (KS_STRIDE * 4) + off * 16,
                           (const void*)&g_Kt[(jb + row) * NC + off * 4]);
            }
#pragma unroll
            for (int i = 0; i < 8; i++) {
                int c = tid + 256 * i;
                int row = c >> 4, off = c & 15;
                CP_ASYNC16(vb + row * (VS_STRIDE * 4) + off * 16,
                           (const void*)&g_V[row * NJ + jb + off * 4]);
            }
            CP_COMMIT();
        }

        // ---- GEMM1: d[16 rows][64 j] over c2=128 (16 k-steps) ----
        float acc1[8][4];
#pragma unroll
        for (int i = 0; i < 8; i++)
#pragma unroll
            for (int k = 0; k < 4; k++) acc1[i][k] = 0.0f;

#pragma unroll
        for (int k = 0; k < 16; k++) {
            uint32_t a[4] = { __float_as_uint(qf0[k].x), __float_as_uint(qf1[k].x),
                              __float_as_uint(qf0[k].y), __float_as_uint(qf1[k].y) };
#pragma unroll
            for (int nt = 0; nt < 8; nt++) {
                float2 b = *reinterpret_cast<const float2*>(
                    &Ks[(nt * 8 + g) * KS_STRIDE + k * 8 + 2 * t]);
                mma8(acc1[nt], a, __float_as_uint(b.x), __float_as_uint(b.y));
            }
        }

        // ---- sigmoid (+tf32 round) on scores ----
#pragma unroll
        for (int i = 0; i < 8; i++)
#pragma unroll
            for (int k = 0; k < 4; k++) acc1[i][k] = tf32r(sigf(acc1[i][k]));

        // ---- GEMM2: O[16 rows][128 c2] += P x V^T over j=64 (8 k-steps) ----
#pragma unroll
        for (int k2 = 0; k2 < 8; k2++) {
            // convert C-fragment acc1[k2] (m16n8) -> A-fragment (m16n8k8)
            float c0 = acc1[k2][0], c1 = acc1[k2][1], c2v = acc1[k2][2], c3v = acc1[k2][3];
            float u0 = __shfl_sync(0xffffffffu, c0, s1l);
            float u1 = __shfl_sync(0xffffffffu, c1, s1l);
            float v0 = __shfl_sync(0xffffffffu, c2v, s1l);
            float v1 = __shfl_sync(0xffffffffu, c3v, s1l);
            float w0 = __shfl_sync(0xffffffffu, c0, s2l);
            float w1 = __shfl_sync(0xffffffffu, c1, s2l);
            float y0 = __shfl_sync(0xffffffffu, c2v, s2l);
            float y1 = __shfl_sync(0xffffffffu, c3v, s2l);
            uint32_t a[4] = { __float_as_uint(odd ? u1 : u0),
                              __float_as_uint(odd ? v1 : v0),
                              __float_as_uint(odd ? w1 : w0),
                              __float_as_uint(odd ? y1 : y0) };
#pragma unroll
            for (int nt = 0; nt < 16; nt++) {
                float2 b = *reinterpret_cast<const float2*>(
                    &Vs[(nt * 8 + g) * VS_STRIDE + k2 * 8 + 2 * t]);
                mma8(acc2[nt], a, __float_as_uint(b.x), __float_as_uint(b.y));
            }
        }

        CP_WAIT0();
        __syncthreads();
    }

    // ---- epilogue: warp-private smem transpose -> coalesced partial stores ----
    float* Osm = sm + warp * 2560;    // [128 c2][20] per warp
#pragma unroll
    for (int nt = 0; nt < 16; nt++) {
        int c2a = nt * 8 + 2 * t;
        Osm[c2a * 20 + g]           = acc2[nt][0];
        Osm[(c2a + 1) * 20 + g]     = acc2[nt][1];
        Osm[c2a * 20 + g + 8]       = acc2[nt][2];
        Osm[(c2a + 1) * 20 + g + 8] = acc2[nt][3];
    }
    __syncwarp();
#pragma unroll
    for (int i = 0; i < 16; i++) {
        int idx = lane + 32 * i;     // 0..511
        int row = idx >> 2, q = idx & 3;
        float4 v = *reinterpret_cast<const float4*>(&Osm[row * 20 + 4 * q]);
        *reinterpret_cast<float4*>(&g_Op[((split << 7) + row) * NN + m0 + wr + 4 * q]) = v;
    }
}

// ---------------------------------------------------------------------------
// Kernel 5: combine partials + residual + S1 -> out [c2][n]
// ---------------------------------------------------------------------------
__global__ void __launch_bounds__(256) reduce_kernel(const float* __restrict__ x,
                                                     float* __restrict__ out) {
    int idx = blockIdx.x * 256 + threadIdx.x;   // float4 units
    int c2 = idx >> 10;
    const float4* x4 = reinterpret_cast<const float4*>(x);
    const float4* o4 = reinterpret_cast<const float4*>(g_Op);
    float4 xv = x4[idx];
    float4 s = make_float4(0.f, 0.f, 0.f, 0.f);
#pragma unroll
    for (int sp = 0; sp < NSPLIT; sp++) {
        float4 v = o4[((sp << 7) + c2) * (NN / 4) + (idx & 1023)];
        s.x += v.x; s.y += v.y; s.z += v.z; s.w += v.w;
    }
    float4 r;
    if (c2 < 64) {
        r.x = xv.x + s.x; r.y = xv.y + s.y; r.z = xv.z + s.z; r.w = xv.w + s.w;
    } else {
        float b = g_S1[c2 - 64];
        r.x = xv.x + b - s.x; r.y = xv.y + b - s.y;
        r.z = xv.z + b - s.z; r.w = xv.w + b - s.w;
    }
    reinterpret_cast<float4*>(out)[idx] = r;
}

// ---------------------------------------------------------------------------
extern "C" void kernel_launch(void* const* d_in, const int* in_sizes, int n_in,
                              void* d_out, int out_size) {
    const float* x  = (const float*)d_in[0];   // [2,64,16,16,16] = [128][4096]
    const float* cw = (const float*)d_in[1];   // [64,64,3]
    const float* cb = (const float*)d_in[2];   // [64]
    float* out = (float*)d_out;

    cudaFuncSetAttribute(conv_kernel, cudaFuncAttributeMaxDynamicSharedMemorySize, CONV_SMEM_BYTES);
    cudaFuncSetAttribute(dspa_main_kernel, cudaFuncAttributeMaxDynamicSharedMemorySize, MAIN_SMEM_BYTES);

    conv_kernel<<<128, 512, CONV_SMEM_BYTES>>>(x, cw, cb);
    s1_kernel<<<64, 256>>>();
    transpose_kernel<<<dim3(128, 4), dim3(32, 8)>>>(x);
    dspa_main_kernel<<<256, 256, MAIN_SMEM_BYTES>>>();
    reduce_kernel<<<512, 256>>>(x, out);
}

// round 6
// speedup vs baseline: 1.1400x; 1.1400x over previous
#include <cuda_runtime.h>
#include <cstdint>

// ============================================================================
// DSPA via mma.sync tf32 (R4 block-synchronous structure + cp.async pipeline
// + pair-permuted LDS.64 fragment layouts + fused transpose + NSPLIT=4):
//   x2 = dilated conv1d(x1); softmax over batch(2) => P = sigmoid(d),
//   d[n,j] = <Q[n], K'[j]>_128,  O[n,c2] = sum_j P[n,j] V[c2,j]
//   out[0,c,n] = x1 + O[n,c];  out[1,c,n] = x1 + S1[c] - O[n,64+c]
// ============================================================================

#define NN 4096
#define NC 128
#define NJ 4096
#define NSPLIT 4
#define JRANGE 1024
#define JSTEP 64
#define NSTEPS 16

__device__ __align__(256) float g_Kt[NJ * NC];          // K'[j][c2-permuted]
__device__ __align__(256) float g_V[NC * NJ];           // V[c2][j-permuted]
__device__ __align__(256) float g_Q[NN * NC];           // Q[n][c2-permuted]
__device__ __align__(256) float g_Op[NSPLIT * NC * NN]; // partial O [s][c2][n]
__device__ float g_S1[64];

// pair-interleave within 8-groups: col c -> (c&3)*2 + (c>>2); float2 at 2t
// then yields logical cols {t, t+4} = exactly one mma fragment pair.
__device__ __forceinline__ int perm8(int c) {
    return (c & ~7) | (((c & 3) << 1) | ((c >> 2) & 1));
}
__device__ __forceinline__ float tf32r(float x) {
    uint32_t r;
    asm("cvt.rna.tf32.f32 %0, %1;" : "=r"(r) : "f"(x));
    return __uint_as_float(r);
}
__device__ __forceinline__ float sigf(float x) {
    return __fdividef(1.0f, 1.0f + __expf(-x));
}
__device__ __forceinline__ void mma8(float* d, const uint32_t* a, uint32_t b0, uint32_t b1) {
    asm volatile(
        "mma.sync.aligned.m16n8k8.row.col.f32.tf32.tf32.f32 "
        "{%0,%1,%2,%3}, {%4,%5,%6,%7}, {%8,%9}, {%0,%1,%2,%3};"
        : "+f"(d[0]), "+f"(d[1]), "+f"(d[2]), "+f"(d[3])
        : "r"(a[0]), "r"(a[1]), "r"(a[2]), "r"(a[3]), "r"(b0), "r"(b1));
}
__device__ __forceinline__ uint32_t smem_u32(const void* p) {
    uint32_t a;
    asm("{ .reg .u64 t; cvta.to.shared.u64 t, %1; cvt.u32.u64 %0, t; }" : "=r"(a) : "l"(p));
    return a;
}
#define CP_ASYNC16(dst, src) \
    asm volatile("cp.async.cg.shared.global [%0], [%1], 16;" :: "r"(dst), "l"(src))
#define CP_COMMIT() asm volatile("cp.async.commit_group;" ::: "memory")
#define CP_WAIT(n)  asm volatile("cp.async.wait_group %0;" :: "n"(n) : "memory")

// ---------------------------------------------------------------------------
// Kernel 1: dilated conv -> K'[j][perm c2], V[c2][perm j] + fused Q transpose
// g_Q[n][perm c2] straight from the already-staged x1s tile.
// grid 128 (32 j per block), block 512.
// ---------------------------------------------------------------------------
#define CONV_SMEM_BYTES ((64 * 195 + 128 * 37) * 4)
__global__ void __launch_bounds__(512) conv_kernel(const float* __restrict__ x,
                                                   const float* __restrict__ w,
                                                   const float* __restrict__ bias) {
    extern __shared__ float sm[];
    float* ws  = sm;             // [64][195]
    float* x1s = sm + 64 * 195;  // [128][37]

    const int tid = threadIdx.x;
    const int j0 = blockIdx.x * 32;

    for (int f = tid; f < 64 * 64 * 3; f += 512) {
        int co = f / 192, rem = f % 192;
        ws[co * 195 + rem] = w[f];
    }
    for (int f = tid; f < 128 * 36; f += 512) {
        int row = f / 36, p = f % 36;
        int pos = j0 - 1 + p;
        x1s[row * 37 + p] = (pos >= 0 && pos < NN) ? x[row * NN + pos] : 0.0f;
    }
    __syncthreads();

    // fused transpose: n in [j0, j0+32) -> x1s col (n-j0+1)
    {
        const int c2q = tid & 127;
        const int c2qp = perm8(c2q);
#pragma unroll
        for (int i = 0; i < 8; i++) {
            int nn = (tid >> 7) + 4 * i;           // 0..31
            g_Q[(j0 + nn) * NC + c2qp] = tf32r(x1s[c2q * 37 + nn + 1]);
        }
    }

    const int c2 = tid & 127;
    const int grp = tid >> 7;
    const int bb = c2 >> 6, co = c2 & 63;
    const int base = grp * 8;
    float acc[8];
    float bv = bias[co];
#pragma unroll
    for (int jj = 0; jj < 8; jj++) acc[jj] = bv;

    for (int ci = 0; ci < 64; ci++) {
        float w0 = ws[co * 195 + ci * 3 + 0];
        float w1 = ws[co * 195 + ci * 3 + 1];
        float w2 = ws[co * 195 + ci * 3 + 2];
        const float* xr = &x1s[(bb * 64 + ci) * 37 + base];
#pragma unroll
        for (int jj = 0; jj < 8; jj++)
            acc[jj] += w0 * xr[jj] + w1 * xr[jj + 2] + w2 * xr[jj + 4];
    }

    const int c2p = perm8(c2);
#pragma unroll
    for (int jj = 0; jj < 8; jj++) {
        int j = j0 + base + jj;
        float v = (j < 4094) ? tf32r(acc[jj]) : 0.0f;
        g_V[c2 * NJ + perm8(j)] = v;
        g_Kt[j * NC + c2p] = (c2 < 64) ? v : -v;
    }
}

// ---------------------------------------------------------------------------
// Kernel 2: S1[c] = sum over V row 64+c (pad entries are zero)
// ---------------------------------------------------------------------------
__global__ void __launch_bounds__(256) s1_kernel() {
    __shared__ float red[256];
    const int c = blockIdx.x;
    float s = 0.0f;
    for (int j = threadIdx.x; j < 4096; j += 256) s += g_V[(64 + c) * NJ + j];
    red[threadIdx.x] = s;
    __syncthreads();
    for (int st = 128; st > 0; st >>= 1) {
        if (threadIdx.x < st) red[threadIdx.x] += red[threadIdx.x + st];
        __syncthreads();
    }
    if (threadIdx.x == 0) g_S1[c] = red[0];
}

// ---------------------------------------------------------------------------
// Kernel 3: main kernel. grid 128 = 32 m-tiles(128n) x 4 j-splits(1024 j),
// block 256 (8 warps = 4m x 2n). One wave on 152 SMs.
// smem floats: Qs[128][132] | Ks[64][132] | Vs 2x[128][68] | Ps[128][68]
// cp.async: V[s] waits before sync1; K[s+1]+V[s+1] commit after sync1;
// K wait_group(1) at step end.
// ---------------------------------------------------------------------------
#define QS_F 0
#define KS_F 16896
#define VS0_F 25344
#define VS1_F 34048
#define PS_F 42752
#define TOT_F 51456
#define MAIN_SMEM_BYTES (TOT_F * 4)   // 205824

__global__ void __launch_bounds__(256, 1) dspa_main_kernel() {
    extern __shared__ float sm[];
    const uint32_t smb = smem_u32(sm);
    float* Qs = sm + QS_F;
    float* Ks = sm + KS_F;
    float* Ps = sm + PS_F;

    const int tid = threadIdx.x;
    const int warp = tid >> 5, lane = tid & 31;
    const int g = lane >> 2, t = lane & 3;
    const int wm = (warp & 3) * 32;
    const int wn1 = (warp >> 2) * 32;
    const int wn2 = (warp >> 2) * 64;
    const int m0 = (blockIdx.x & 31) << 7;
    const int split = blockIdx.x >> 5;
    const int jb0 = split * JRANGE;

    // in-group storage columns for P writes (logical cols 2t, 2t+1)
    const int pc0 = (((2 * t) & 3) << 1) | ((2 * t) >> 2);
    const int pc1 = (((2 * t + 1) & 3) << 1) | ((2 * t + 1) >> 2);

    // ---- preamble: commit K[0] (group), V[0] (group); stage Qs; wait ----
#pragma unroll
    for (int i = 0; i < 8; i++) {
        int c = tid + 256 * i;                 // K: 64 rows x 32 chunks
        int row = c >> 5, off = c & 31;
        CP_ASYNC16(smb + KS_F * 4 + row * (132 * 4) + off * 16,
                   (const void*)&g_Kt[(jb0 + row) * NC + off * 4]);
    }
    CP_COMMIT();
#pragma unroll
    for (int i = 0; i < 8; i++) {
        int c = tid + 256 * i;                 // V: 128 rows x 16 chunks
        int row = c >> 4, off = c & 15;
        CP_ASYNC16(smb + VS0_F * 4 + row * (68 * 4) + off * 16,
                   (const void*)&g_V[row * NJ + jb0 + off * 4]);
    }
    CP_COMMIT();
#pragma unroll
    for (int it = 0; it < 16; it++) {
        int idx = it * 256 + tid;
        int r = idx >> 5, q = idx & 31;
        float4 v = *reinterpret_cast<const float4*>(&g_Q[(m0 + r) * NC + 4 * q]);
        *reinterpret_cast<float4*>(&Qs[r * 132 + 4 * q]) = v;
    }
    CP_WAIT(0);
    __syncthreads();

    float acc2[16][4];
#pragma unroll
    for (int i = 0; i < 16; i++)
#pragma unroll
        for (int k = 0; k < 4; k++) acc2[i][k] = 0.0f;

    for (int s = 0; s < NSTEPS; s++) {
        float* Vs = sm + ((s & 1) ? VS1_F : VS0_F);

        // ---- GEMM1: d[128n x 64j] over c2=128, LDS.64 fragments ----
        float acc1[8][4];
#pragma unroll
        for (int i = 0; i < 8; i++)
#pragma unroll
            for (int k = 0; k < 4; k++) acc1[i][k] = 0.0f;

#pragma unroll
        for (int k0 = 0; k0 < 16; k0++) {
            uint32_t a[2][4];
#pragma unroll
            for (int mt = 0; mt < 2; mt++) {
                float2 q0 = *reinterpret_cast<const float2*>(
                    &Qs[(wm + mt * 16 + g) * 132 + k0 * 8 + 2 * t]);
                float2 q1 = *reinterpret_cast<const float2*>(
                    &Qs[(wm + mt * 16 + g + 8) * 132 + k0 * 8 + 2 * t]);
                a[mt][0] = __float_as_uint(q0.x); a[mt][1] = __float_as_uint(q1.x);
                a[mt][2] = __float_as_uint(q0.y); a[mt][3] = __float_as_uint(q1.y);
            }
#pragma unroll
            for (int nt = 0; nt < 4; nt++) {
                float2 b = *reinterpret_cast<const float2*>(
                    &Ks[(wn1 + nt * 8 + g) * 132 + k0 * 8 + 2 * t]);
#pragma unroll
                for (int mt = 0; mt < 2; mt++)
                    mma8(acc1[mt * 4 + nt], a[mt],
                         __float_as_uint(b.x), __float_as_uint(b.y));
            }
        }

        // sigmoid then store P at pair-permuted positions
#pragma unroll
        for (int i = 0; i < 8; i++)
#pragma unroll
            for (int k = 0; k < 4; k++) acc1[i][k] = tf32r(sigf(acc1[i][k]));
#pragma unroll
        for (int mt = 0; mt < 2; mt++)
#pragma unroll
            for (int nt = 0; nt < 4; nt++) {
                int rn = wm + mt * 16 + g;
                int cb = wn1 + nt * 8;
                const float* c = acc1[mt * 4 + nt];
                Ps[rn * 68 + cb + pc0]       = c[0];
                Ps[rn * 68 + cb + pc1]       = c[1];
                Ps[(rn + 8) * 68 + cb + pc0] = c[2];
                Ps[(rn + 8) * 68 + cb + pc1] = c[3];
            }

        CP_WAIT(0);          // V[s] (and any older) complete
        __syncthreads();     // P + V visible to all

        // prefetch K[s+1] (group), V[s+1] (group)
        if (s + 1 < NSTEPS) {
            const int jb = jb0 + (s + 1) * JSTEP;
            uint32_t vdst = smb + (((s + 1) & 1) ? VS1_F : VS0_F) * 4;
#pragma unroll
            for (int i = 0; i < 8; i++) {
                int c = tid + 256 * i;
                int row = c >> 5, off = c & 31;
                CP_ASYNC16(smb + KS_F * 4 + row * (132 * 4) + off * 16,
                           (const void*)&g_Kt[(jb + row) * NC + off * 4]);
            }
            CP_COMMIT();
#pragma unroll
            for (int i = 0; i < 8; i++) {
                int c = tid + 256 * i;
                int row = c >> 4, off = c & 15;
                CP_ASYNC16(vdst + row * (68 * 4) + off * 16,
                           (const void*)&g_V[row * NJ + jb + off * 4]);
            }
            CP_COMMIT();
        }

        // ---- GEMM2: O[128n x 128c2] += P x V^T over j=64 ----
#pragma unroll
        for (int k0 = 0; k0 < 8; k0++) {
            uint32_t a[2][4];
#pragma unroll
            for (int mt = 0; mt < 2; mt++) {
                float2 p0 = *reinterpret_cast<const float2*>(
                    &Ps[(wm + mt * 16 + g) * 68 + k0 * 8 + 2 * t]);
                float2 p1 = *reinterpret_cast<const float2*>(
                    &Ps[(wm + mt * 16 + g + 8) * 68 + k0 * 8 + 2 * t]);
                a[mt][0] = __float_as_uint(p0.x); a[mt][1] = __float_as_uint(p1.x);
                a[mt][2] = __float_as_uint(p0.y); a[mt][3] = __float_as_uint(p1.y);
            }
#pragma unroll
            for (int nt = 0; nt < 8; nt++) {
                float2 b = *reinterpret_cast<const float2*>(
                    &Vs[(wn2 + nt * 8 + g) * 68 + k0 * 8 + 2 * t]);
#pragma unroll
                for (int mt = 0; mt < 2; mt++)
                    mma8(acc2[mt * 8 + nt], a[mt],
                         __float_as_uint(b.x), __float_as_uint(b.y));
            }
        }

        CP_WAIT(1);          // K[s+1] arrived (V[s+1] may still fly)
        __syncthreads();     // K visible; P/V free for rewrite
    }

    // ---- epilogue: fragments -> smem [c2][n] -> coalesced partial stores ----
    float* Osm = sm;   // [128][129] floats, reuses Qs region
#pragma unroll
    for (int mt = 0; mt < 2; mt++)
#pragma unroll
        for (int nt = 0; nt < 8; nt++) {
            int n = wm + mt * 16 + g;
            int c2 = wn2 + nt * 8 + 2 * t;
            const float* c = acc2[mt * 8 + nt];
            Osm[c2 * 129 + n]           = c[0];
            Osm[(c2 + 1) * 129 + n]     = c[1];
            Osm[c2 * 129 + n + 8]       = c[2];
            Osm[(c2 + 1) * 129 + n + 8] = c[3];
        }
    __syncthreads();
#pragma unroll
    for (int it = 0; it < 16; it++) {
        int idx = it * 256 + tid;
        int r = idx >> 5, q = idx & 31;
        float4 v = make_float4(Osm[r * 129 + 4 * q], Osm[r * 129 + 4 * q + 1],
                               Osm[r * 129 + 4 * q + 2], Osm[r * 129 + 4 * q + 3]);
        *reinterpret_cast<float4*>(&g_Op[((split << 7) + r) * NN + m0 + 4 * q]) = v;
    }
}

// ---------------------------------------------------------------------------
// Kernel 4: combine partials + residual + S1 -> out [c2][n]
// ---------------------------------------------------------------------------
__global__ void __launch_bounds__(256) reduce_kernel(const float* __restrict__ x,
                                                     float* __restrict__ out) {
    int idx = blockIdx.x * 256 + threadIdx.x;   // float4 units
    int c2 = idx >> 10;
    const float4* x4 = reinterpret_cast<const float4*>(x);
    const float4* o4 = reinterpret_cast<const float4*>(g_Op);
    float4 xv = x4[idx];
    float4 s = make_float4(0.f, 0.f, 0.f, 0.f);
#pragma unroll
    for (int sp = 0; sp < NSPLIT; sp++) {
        float4 v = o4[((sp << 7) + c2) * (NN / 4) + (idx & 1023)];
        s.x += v.x; s.y += v.y; s.z += v.z; s.w += v.w;
    }
    float4 r;
    if (c2 < 64) {
        r.x = xv.x + s.x; r.y = xv.y + s.y; r.z = xv.z + s.z; r.w = xv.w + s.w;
    } else {
        float b = g_S1[c2 - 64];
        r.x = xv.x + b - s.x; r.y = xv.y + b - s.y;
        r.z = xv.z + b - s.z; r.w = xv.w + b - s.w;
    }
    reinterpret_cast<float4*>(out)[idx] = r;
}

// ---------------------------------------------------------------------------
extern "C" void kernel_launch(void* const* d_in, const int* in_sizes, int n_in,
                              void* d_out, int out_size) {
    const float* x  = (const float*)d_in[0];   // [2,64,16,16,16] = [128][4096]
    const float* cw = (const float*)d_in[1];   // [64,64,3]
    const float* cb = (const float*)d_in[2];   // [64]
    float* out = (float*)d_out;

    cudaFuncSetAttribute(conv_kernel, cudaFuncAttributeMaxDynamicSharedMemorySize, CONV_SMEM_BYTES);
    cudaFuncSetAttribute(dspa_main_kernel, cudaFuncAttributeMaxDynamicSharedMemorySize, MAIN_SMEM_BYTES);

    conv_kernel<<<128, 512, CONV_SMEM_BYTES>>>(x, cw, cb);
    s1_kernel<<<64, 256>>>();
    dspa_main_kernel<<<128, 256, MAIN_SMEM_BYTES>>>();
    reduce_kernel<<<512, 256>>>(x, out);
}

// round 9
// speedup vs baseline: 1.2533x; 1.0994x over previous
#include <cuda_runtime.h>
#include <cstdint>

// ============================================================================
// DSPA via mma.sync tf32 — R4 structure/layout (proven), 16 warps per CTA
// (4/SMSP) for latency hiding, NSPLIT=4 single-wave grid:
//   x2 = dilated conv1d(x1); softmax over batch(2) => P = sigmoid(d),
//   d[n,j] = <Q[n], K'[j]>_128,  O[n,c2] = sum_j P[n,j] V[c2,j]
//   out[0,c,n] = x1 + O[n,c];  out[1,c,n] = x1 + S1[c] - O[n,64+c]
// ============================================================================

#define NN 4096
#define NC 128
#define NJ 4096
#define NSPLIT 4
#define JRANGE 1024
#define JSTEP 64
#define NSTEPS 16

__device__ __align__(256) float g_Kt[NJ * NC];          // K'[j][c2]
__device__ __align__(256) float g_V[NC * NJ];           // V[c2][j]
__device__ __align__(256) float g_Q[NN * NC];           // Q[n][c2]
__device__ __align__(256) float g_Op[NSPLIT * NC * NN]; // partial O [s][c2][n]
__device__ float g_S1[64];

__device__ __forceinline__ float tf32r(float x) {
    uint32_t r;
    asm("cvt.rna.tf32.f32 %0, %1;" : "=r"(r) : "f"(x));
    return __uint_as_float(r);
}
__device__ __forceinline__ float sigf(float x) {
    return __fdividef(1.0f, 1.0f + __expf(-x));
}
__device__ __forceinline__ void mma8(float* d, const uint32_t* a, uint32_t b0, uint32_t b1) {
    asm volatile(
        "mma.sync.aligned.m16n8k8.row.col.f32.tf32.tf32.f32 "
        "{%0,%1,%2,%3}, {%4,%5,%6,%7}, {%8,%9}, {%0,%1,%2,%3};"
        : "+f"(d[0]), "+f"(d[1]), "+f"(d[2]), "+f"(d[3])
        : "r"(a[0]), "r"(a[1]), "r"(a[2]), "r"(a[3]), "r"(b0), "r"(b1));
}

// ---------------------------------------------------------------------------
// Kernel 1: dilated conv -> K'[j][c2], V[c2][j] + fused Q transpose
// grid 128 (32 j per block), block 512.
// ---------------------------------------------------------------------------
#define CONV_SMEM_BYTES ((64 * 195 + 128 * 37) * 4)
__global__ void __launch_bounds__(512) conv_kernel(const float* __restrict__ x,
                                                   const float* __restrict__ w,
                                                   const float* __restrict__ bias) {
    extern __shared__ float sm[];
    float* ws  = sm;             // [64][195]
    float* x1s = sm + 64 * 195;  // [128][37]

    const int tid = threadIdx.x;
    const int j0 = blockIdx.x * 32;

    for (int f = tid; f < 64 * 64 * 3; f += 512) {
        int co = f / 192, rem = f % 192;
        ws[co * 195 + rem] = w[f];
    }
    for (int f = tid; f < 128 * 36; f += 512) {
        int row = f / 36, p = f % 36;
        int pos = j0 - 1 + p;
        x1s[row * 37 + p] = (pos >= 0 && pos < NN) ? x[row * NN + pos] : 0.0f;
    }
    __syncthreads();

    // fused transpose: g_Q[n][c2] for n in [j0, j0+32) from staged x1s
    {
        const int c2q = tid & 127;
#pragma unroll
        for (int i = 0; i < 8; i++) {
            int nn = (tid >> 7) + 4 * i;           // 0..31
            g_Q[(j0 + nn) * NC + c2q] = tf32r(x1s[c2q * 37 + nn + 1]);
        }
    }

    const int c2 = tid & 127;
    const int grp = tid >> 7;
    const int bb = c2 >> 6, co = c2 & 63;
    const int base = grp * 8;
    float acc[8];
    float bv = bias[co];
#pragma unroll
    for (int jj = 0; jj < 8; jj++) acc[jj] = bv;

    for (int ci = 0; ci < 64; ci++) {
        float w0 = ws[co * 195 + ci * 3 + 0];
        float w1 = ws[co * 195 + ci * 3 + 1];
        float w2 = ws[co * 195 + ci * 3 + 2];
        const float* xr = &x1s[(bb * 64 + ci) * 37 + base];
#pragma unroll
        for (int jj = 0; jj < 8; jj++)
            acc[jj] += w0 * xr[jj] + w1 * xr[jj + 2] + w2 * xr[jj + 4];
    }

#pragma unroll
    for (int jj = 0; jj < 8; jj++) {
        int j = j0 + base + jj;
        float v = (j < 4094) ? tf32r(acc[jj]) : 0.0f;   // zero-pad tail
        g_V[c2 * NJ + j] = v;
        g_Kt[j * NC + c2] = (c2 < 64) ? v : -v;
    }
}

// ---------------------------------------------------------------------------
// Kernel 2: S1[c] = sum over V row 64+c (pad entries are zero)
// ---------------------------------------------------------------------------
__global__ void __launch_bounds__(256) s1_kernel() {
    __shared__ float red[256];
    const int c = blockIdx.x;
    float s = 0.0f;
    for (int j = threadIdx.x; j < 4096; j += 256) s += g_V[(64 + c) * NJ + j];
    red[threadIdx.x] = s;
    __syncthreads();
    for (int st = 128; st > 0; st >>= 1) {
        if (threadIdx.x < st) red[threadIdx.x] += red[threadIdx.x + st];
        __syncthreads();
    }
    if (threadIdx.x == 0) g_S1[c] = red[0];
}

// ---------------------------------------------------------------------------
// Kernel 3: main kernel. grid 128 = 32 m-tiles(128n) x 4 j-splits(1024 j).
// block 512 = 16 warps = 4m x 4n. Warp tiles: G1 32n x 16j, G2 32n x 32c2.
// smem floats: Qs[128][132] | Ks[64][132] | Vs[128][68] | Ps[128][68]
// (strides ≡4 mod 32 -> LDS.32 fragment loads hit 32 distinct banks)
// ---------------------------------------------------------------------------
#define QS_F 0
#define KS_F 16896
#define VS_F 25344
#define PS_F 34048
#define TOT_F 42752
#define MAIN_SMEM_BYTES (TOT_F * 4)   // 171008

__global__ void __launch_bounds__(512, 1) dspa_main_kernel() {
    extern __shared__ float sm[];
    float* Qs = sm + QS_F;
    float* Ks = sm + KS_F;
    float* Vs = sm + VS_F;
    float* Ps = sm + PS_F;

    const int tid = threadIdx.x;
    const int warp = tid >> 5, lane = tid & 31;
    const int g = lane >> 2, t = lane & 3;
    const int wm = (warp & 3) * 32;        // 4 m-rows of warps, 32 n each
    const int wn1 = (warp >> 2) * 16;      // G1: 16 j-cols each
    const int wn2 = (warp >> 2) * 32;      // G2: 32 c2-cols each
    const int m0 = (blockIdx.x & 31) << 7;
    const int split = blockIdx.x >> 5;
    const int jb0 = split * JRANGE;

    // stage Q tile [128][128]
#pragma unroll
    for (int it = 0; it < 8; it++) {
        int idx = it * 512 + tid;          // 0..4095 float4 chunks
        int r = idx >> 5, q = idx & 31;
        float4 v = *reinterpret_cast<const float4*>(&g_Q[(m0 + r) * NC + 4 * q]);
        *reinterpret_cast<float4*>(&Qs[r * 132 + 4 * q]) = v;
    }

    float acc2[8][4];
#pragma unroll
    for (int i = 0; i < 8; i++)
#pragma unroll
        for (int k = 0; k < 4; k++) acc2[i][k] = 0.0f;

    for (int s = 0; s < NSTEPS; s++) {
        const int jb = jb0 + s * JSTEP;
        __syncthreads();   // prior step's reads of Ks/Vs/Ps done (Q staged, s=0)
        // stage K [64 j][128 c2] and V [128 c2][64 j]
#pragma unroll
        for (int it = 0; it < 4; it++) {
            int idx = it * 512 + tid;      // 0..2047
            {
                int r = idx >> 5, q = idx & 31;
                float4 v = *reinterpret_cast<const float4*>(&g_Kt[(jb + r) * NC + 4 * q]);
                *reinterpret_cast<float4*>(&Ks[r * 132 + 4 * q]) = v;
            }
            {
                int r = idx >> 4, q = idx & 15;
                float4 v = *reinterpret_cast<const float4*>(&g_V[r * NJ + jb + 4 * q]);
                *reinterpret_cast<float4*>(&Vs[r * 68 + 4 * q]) = v;
            }
        }
        __syncthreads();

        // ---- GEMM1: warp computes d[32n x 16j] over c2=128 ----
        float acc1[4][4];
#pragma unroll
        for (int i = 0; i < 4; i++)
#pragma unroll
            for (int k = 0; k < 4; k++) acc1[i][k] = 0.0f;

#pragma unroll
        for (int k0 = 0; k0 < 128; k0 += 8) {
            uint32_t a[2][4];
#pragma unroll
            for (int mt = 0; mt < 2; mt++) {
                const float* q0 = &Qs[(wm + mt * 16 + g) * 132 + k0 + t];
                const float* q1 = q0 + 8 * 132;
                a[mt][0] = __float_as_uint(q0[0]);
                a[mt][1] = __float_as_uint(q1[0]);
                a[mt][2] = __float_as_uint(q0[4]);
                a[mt][3] = __float_as_uint(q1[4]);
            }
#pragma unroll
            for (int nt = 0; nt < 2; nt++) {
                const float* kp = &Ks[(wn1 + nt * 8 + g) * 132 + k0 + t];
                uint32_t b0 = __float_as_uint(kp[0]);
                uint32_t b1 = __float_as_uint(kp[4]);
#pragma unroll
                for (int mt = 0; mt < 2; mt++)
                    mma8(acc1[mt * 2 + nt], a[mt], b0, b1);
            }
        }

        // sigmoid + store P
#pragma unroll
        for (int mt = 0; mt < 2; mt++)
#pragma unroll
            for (int nt = 0; nt < 2; nt++) {
                int rn = wm + mt * 16 + g;
                int cj = wn1 + nt * 8 + 2 * t;
                float* c = acc1[mt * 2 + nt];
                Ps[rn * 68 + cj]           = tf32r(sigf(c[0]));
                Ps[rn * 68 + cj + 1]       = tf32r(sigf(c[1]));
                Ps[(rn + 8) * 68 + cj]     = tf32r(sigf(c[2]));
                Ps[(rn + 8) * 68 + cj + 1] = tf32r(sigf(c[3]));
            }
        __syncthreads();

        // ---- GEMM2: warp accumulates O[32n x 32c2] over j=64 ----
#pragma unroll
        for (int k0 = 0; k0 < 64; k0 += 8) {
            uint32_t a[2][4];
#pragma unroll
            for (int mt = 0; mt < 2; mt++) {
                const float* p0 = &Ps[(wm + mt * 16 + g) * 68 + k0 + t];
                const float* p1 = p0 + 8 * 68;
                a[mt][0] = __float_as_uint(p0[0]);
                a[mt][1] = __float_as_uint(p1[0]);
                a[mt][2] = __float_as_uint(p0[4]);
                a[mt][3] = __float_as_uint(p1[4]);
            }
#pragma unroll
            for (int nt = 0; nt < 4; nt++) {
                const float* vp = &Vs[(wn2 + nt * 8 + g) * 68 + k0 + t];
                uint32_t b0 = __float_as_uint(vp[0]);
                uint32_t b1 = __float_as_uint(vp[4]);
#pragma unroll
                for (int mt = 0; mt < 2; mt++)
                    mma8(acc2[mt * 4 + nt], a[mt], b0, b1);
            }
        }
    }

    // ---- epilogue: fragments -> smem [c2][n] -> coalesced partial stores ----
    __syncthreads();
    float* Osm = sm;   // [128][129] floats, reuses Qs region
#pragma unroll
    for (int mt = 0; mt < 2; mt++)
#pragma unroll
        for (int nt = 0; nt < 4; nt++) {
            int n = wm + mt * 16 + g;
            int c2 = wn2 + nt * 8 + 2 * t;
            const float* c = acc2[mt * 4 + nt];
            Osm[c2 * 129 + n]           = c[0];
            Osm[(c2 + 1) * 129 + n]     = c[1];
            Osm[c2 * 129 + n + 8]       = c[2];
            Osm[(c2 + 1) * 129 + n + 8] = c[3];
        }
    __syncthreads();
#pragma unroll
    for (int it = 0; it < 8; it++) {
        int idx = it * 512 + tid;
        int r = idx >> 5, q = idx & 31;
        float4 v = make_float4(Osm[r * 129 + 4 * q], Osm[r * 129 + 4 * q + 1],
                               Osm[r * 129 + 4 * q + 2], Osm[r * 129 + 4 * q + 3]);
        *reinterpret_cast<float4*>(&g_Op[((split << 7) + r) * NN + m0 + 4 * q]) = v;
    }
}

// ---------------------------------------------------------------------------
// Kernel 4: combine partials + residual + S1 -> out [c2][n]
// ---------------------------------------------------------------------------
__global__ void __launch_bounds__(256) reduce_kernel(const float* __restrict__ x,
                                                     float* __restrict__ out) {
    int idx = blockIdx.x * 256 + threadIdx.x;   // float4 units
    int c2 = idx >> 10;
    const float4* x4 = reinterpret_cast<const float4*>(x);
    const float4* o4 = reinterpret_cast<const float4*>(g_Op);
    float4 xv = x4[idx];
    float4 s = make_float4(0.f, 0.f, 0.f, 0.f);
#pragma unroll
    for (int sp = 0; sp < NSPLIT; sp++) {
        float4 v = o4[((sp << 7) + c2) * (NN / 4) + (idx & 1023)];
        s.x += v.x; s.y += v.y; s.z += v.z; s.w += v.w;
    }
    float4 r;
    if (c2 < 64) {
        r.x = xv.x + s.x; r.y = xv.y + s.y; r.z = xv.z + s.z; r.w = xv.w + s.w;
    } else {
        float b = g_S1[c2 - 64];
        r.x = xv.x + b - s.x; r.y = xv.y + b - s.y;
        r.z = xv.z + b - s.z; r.w = xv.w + b - s.w;
    }
    reinterpret_cast<float4*>(out)[idx] = r;
}

// ---------------------------------------------------------------------------
extern "C" void kernel_launch(void* const* d_in, const int* in_sizes, int n_in,
                              void* d_out, int out_size) {
    const float* x  = (const float*)d_in[0];   // [2,64,16,16,16] = [128][4096]
    const float* cw = (const float*)d_in[1];   // [64,64,3]
    const float* cb = (const float*)d_in[2];   // [64]
    float* out = (float*)d_out;

    cudaFuncSetAttribute(conv_kernel, cudaFuncAttributeMaxDynamicSharedMemorySize, CONV_SMEM_BYTES);
    cudaFuncSetAttribute(dspa_main_kernel, cudaFuncAttributeMaxDynamicSharedMemorySize, MAIN_SMEM_BYTES);

    conv_kernel<<<128, 512, CONV_SMEM_BYTES>>>(x, cw, cb);
    s1_kernel<<<64, 256>>>();
    dspa_main_kernel<<<128, 512, MAIN_SMEM_BYTES>>>();
    reduce_kernel<<<512, 256>>>(x, out);
}

// round 12
// speedup vs baseline: 1.4484x; 1.1557x over previous
#include <cuda_runtime.h>
#include <cstdint>

// ============================================================================
// DSPA via mma.sync tf32 — R4 compute body (proven tiling, conflict-free
// LDS.32 strides) + cp.async pipelined K/V staging (K single-buf committed
// mid-step, V double-buf), NSPLIT=4 single-wave grid:
//   x2 = dilated conv1d(x1); softmax over batch(2) => P = sigmoid(d),
//   d[n,j] = <Q[n], K'[j]>_128,  O[n,c2] = sum_j P[n,j] V[c2,j]
//   out[0,c,n] = x1 + O[n,c];  out[1,c,n] = x1 + S1[c] - O[n,64+c]
// ============================================================================

#define NN 4096
#define NC 128
#define NJ 4096
#define NSPLIT 4
#define JRANGE 1024
#define JSTEP 64
#define NSTEPS 16

__device__ __align__(256) float g_Kt[NJ * NC];          // K'[j][c2]
__device__ __align__(256) float g_V[NC * NJ];           // V[c2][j]
__device__ __align__(256) float g_Q[NN * NC];           // Q[n][c2]
__device__ __align__(256) float g_Op[NSPLIT * NC * NN]; // partial O [s][c2][n]
__device__ float g_S1[64];

__device__ __forceinline__ float tf32r(float x) {
    uint32_t r;
    asm("cvt.rna.tf32.f32 %0, %1;" : "=r"(r) : "f"(x));
    return __uint_as_float(r);
}
__device__ __forceinline__ float sigf(float x) {
    return __fdividef(1.0f, 1.0f + __expf(-x));
}
__device__ __forceinline__ void mma8(float* d, const uint32_t* a, uint32_t b0, uint32_t b1) {
    asm volatile(
        "mma.sync.aligned.m16n8k8.row.col.f32.tf32.tf32.f32 "
        "{%0,%1,%2,%3}, {%4,%5,%6,%7}, {%8,%9}, {%0,%1,%2,%3};"
        : "+f"(d[0]), "+f"(d[1]), "+f"(d[2]), "+f"(d[3])
        : "r"(a[0]), "r"(a[1]), "r"(a[2]), "r"(a[3]), "r"(b0), "r"(b1));
}
__device__ __forceinline__ uint32_t smem_u32(const void* p) {
    uint32_t a;
    asm("{ .reg .u64 t; cvta.to.shared.u64 t, %1; cvt.u32.u64 %0, t; }" : "=r"(a) : "l"(p));
    return a;
}
#define CP_ASYNC16(dst, src) \
    asm volatile("cp.async.cg.shared.global [%0], [%1], 16;" :: "r"(dst), "l"(src))
#define CP_COMMIT() asm volatile("cp.async.commit_group;" ::: "memory")
#define CP_WAIT0()  asm volatile("cp.async.wait_group 0;" ::: "memory")

// ---------------------------------------------------------------------------
// Kernel 1: dilated conv -> K'[j][c2], V[c2][j] + fused Q transpose
// grid 128 (32 j per block), block 512.
// ---------------------------------------------------------------------------
#define CONV_SMEM_BYTES ((64 * 195 + 128 * 37) * 4)
__global__ void __launch_bounds__(512) conv_kernel(const float* __restrict__ x,
                                                   const float* __restrict__ w,
                                                   const float* __restrict__ bias) {
    extern __shared__ float sm[];
    float* ws  = sm;             // [64][195]
    float* x1s = sm + 64 * 195;  // [128][37]

    const int tid = threadIdx.x;
    const int j0 = blockIdx.x * 32;

    for (int f = tid; f < 64 * 64 * 3; f += 512) {
        int co = f / 192, rem = f % 192;
        ws[co * 195 + rem] = w[f];
    }
    for (int f = tid; f < 128 * 36; f += 512) {
        int row = f / 36, p = f % 36;
        int pos = j0 - 1 + p;
        x1s[row * 37 + p] = (pos >= 0 && pos < NN) ? x[row * NN + pos] : 0.0f;
    }
    __syncthreads();

    // fused transpose: g_Q[n][c2] for n in [j0, j0+32) from staged x1s
    {
        const int c2q = tid & 127;
#pragma unroll
        for (int i = 0; i < 8; i++) {
            int nn = (tid >> 7) + 4 * i;           // 0..31
            g_Q[(j0 + nn) * NC + c2q] = tf32r(x1s[c2q * 37 + nn + 1]);
        }
    }

    const int c2 = tid & 127;
    const int grp = tid >> 7;
    const int bb = c2 >> 6, co = c2 & 63;
    const int base = grp * 8;
    float acc[8];
    float bv = bias[co];
#pragma unroll
    for (int jj = 0; jj < 8; jj++) acc[jj] = bv;

    for (int ci = 0; ci < 64; ci++) {
        float w0 = ws[co * 195 + ci * 3 + 0];
        float w1 = ws[co * 195 + ci * 3 + 1];
        float w2 = ws[co * 195 + ci * 3 + 2];
        const float* xr = &x1s[(bb * 64 + ci) * 37 + base];
#pragma unroll
        for (int jj = 0; jj < 8; jj++)
            acc[jj] += w0 * xr[jj] + w1 * xr[jj + 2] + w2 * xr[jj + 4];
    }

#pragma unroll
    for (int jj = 0; jj < 8; jj++) {
        int j = j0 + base + jj;
        float v = (j < 4094) ? tf32r(acc[jj]) : 0.0f;   // zero-pad tail
        g_V[c2 * NJ + j] = v;
        g_Kt[j * NC + c2] = (c2 < 64) ? v : -v;
    }
}

// ---------------------------------------------------------------------------
// Kernel 2: S1[c] = sum over V row 64+c (pad entries are zero)
// ---------------------------------------------------------------------------
__global__ void __launch_bounds__(256) s1_kernel() {
    __shared__ float red[256];
    const int c = blockIdx.x;
    float s = 0.0f;
    for (int j = threadIdx.x; j < 4096; j += 256) s += g_V[(64 + c) * NJ + j];
    red[threadIdx.x] = s;
    __syncthreads();
    for (int st = 128; st > 0; st >>= 1) {
        if (threadIdx.x < st) red[threadIdx.x] += red[threadIdx.x + st];
        __syncthreads();
    }
    if (threadIdx.x == 0) g_S1[c] = red[0];
}

// ---------------------------------------------------------------------------
// Kernel 3: main kernel. grid 128 = 32 m-tiles(128n) x 4 j-splits(1024 j).
// block 256 = 8 warps = 4m x 2n (R4 tiling: G1 32n x 32j, G2 32n x 64c2).
// smem floats: Qs[128][132] | Ks[64][132] | Vs 2x[128][68] | Ps[128][68]
// Pipeline: [wait0;sync] G1; sigmoid; Pstore; [sync]; commit K(s+1),V(s+1);
// G2.  K single-buffered, V double-buffered.
// ---------------------------------------------------------------------------
#define QS_F 0
#define KS_F 16896
#define VS0_F 25344
#define VS1_F 34048
#define PS_F 42752
#define TOT_F 51456
#define MAIN_SMEM_BYTES (TOT_F * 4)   // 205824

__global__ void __launch_bounds__(256, 1) dspa_main_kernel() {
    extern __shared__ float sm[];
    const uint32_t smb = smem_u32(sm);
    float* Qs = sm + QS_F;
    float* Ks = sm + KS_F;
    float* Ps = sm + PS_F;

    const int tid = threadIdx.x;
    const int warp = tid >> 5, lane = tid & 31;
    const int g = lane >> 2, t = lane & 3;
    const int wm = (warp & 3) * 32;
    const int wn1 = (warp >> 2) * 32;
    const int wn2 = (warp >> 2) * 64;
    const int m0 = (blockIdx.x & 31) << 7;
    const int split = blockIdx.x >> 5;
    const int jb0 = split * JRANGE;

    // ---- prologue: cp.async K(0), V(0); stage Qs; wait; sync ----
#pragma unroll
    for (int i = 0; i < 8; i++) {
        int c = tid + 256 * i;                 // K: 64 rows x 32 float4 chunks
        int row = c >> 5, off = c & 31;
        CP_ASYNC16(smb + KS_F * 4 + row * (132 * 4) + off * 16,
                   (const void*)&g_Kt[(jb0 + row) * NC + off * 4]);
    }
    CP_COMMIT();
#pragma unroll
    for (int i = 0; i < 8; i++) {
        int c = tid + 256 * i;                 // V: 128 rows x 16 chunks
        int row = c >> 4, off = c & 15;
        CP_ASYNC16(smb + VS0_F * 4 + row * (68 * 4) + off * 16,
                   (const void*)&g_V[row * NJ + jb0 + off * 4]);
    }
    CP_COMMIT();
#pragma unroll
    for (int it = 0; it < 16; it++) {
        int idx = it * 256 + tid;              // Q: 128 rows x 32 chunks
        int r = idx >> 5, q = idx & 31;
        float4 v = *reinterpret_cast<const float4*>(&g_Q[(m0 + r) * NC + 4 * q]);
        *reinterpret_cast<float4*>(&Qs[r * 132 + 4 * q]) = v;
    }

    float acc2[16][4];
#pragma unroll
    for (int i = 0; i < 16; i++)
#pragma unroll
        for (int k = 0; k < 4; k++) acc2[i][k] = 0.0f;

    for (int s = 0; s < NSTEPS; s++) {
        float* Vs = sm + ((s & 1) ? VS1_F : VS0_F);

        CP_WAIT0();          // K(s) and V(s) (committed last step) arrived
        __syncthreads();     // also: G2(s-1) done reading V(s-1)/P(s-1)

        // ---- GEMM1: warp computes d[32n x 32j] over c2=128 ----
        float acc1[8][4];
#pragma unroll
        for (int i = 0; i < 8; i++)
#pragma unroll
            for (int k = 0; k < 4; k++) acc1[i][k] = 0.0f;

#pragma unroll
        for (int k0 = 0; k0 < 128; k0 += 8) {
            uint32_t a[2][4];
#pragma unroll
            for (int mt = 0; mt < 2; mt++) {
                const float* q0 = &Qs[(wm + mt * 16 + g) * 132 + k0 + t];
                const float* q1 = q0 + 8 * 132;
                a[mt][0] = __float_as_uint(q0[0]);
                a[mt][1] = __float_as_uint(q1[0]);
                a[mt][2] = __float_as_uint(q0[4]);
                a[mt][3] = __float_as_uint(q1[4]);
            }
#pragma unroll
            for (int nt = 0; nt < 4; nt++) {
                const float* kp = &Ks[(wn1 + nt * 8 + g) * 132 + k0 + t];
                uint32_t b0 = __float_as_uint(kp[0]);
                uint32_t b1 = __float_as_uint(kp[4]);
#pragma unroll
                for (int mt = 0; mt < 2; mt++)
                    mma8(acc1[mt * 4 + nt], a[mt], b0, b1);
            }
        }

        // sigmoid + store P
#pragma unroll
        for (int mt = 0; mt < 2; mt++)
#pragma unroll
            for (int nt = 0; nt < 4; nt++) {
                int rn = wm + mt * 16 + g;
                int cj = wn1 + nt * 8 + 2 * t;
                float* c = acc1[mt * 4 + nt];
                Ps[rn * 68 + cj]           = tf32r(sigf(c[0]));
                Ps[rn * 68 + cj + 1]       = tf32r(sigf(c[1]));
                Ps[(rn + 8) * 68 + cj]     = tf32r(sigf(c[2]));
                Ps[(rn + 8) * 68 + cj + 1] = tf32r(sigf(c[3]));
            }
        __syncthreads();     // P visible; all G1 reads of Ks done

        // prefetch K(s+1) (single buffer, safe now) and V(s+1) (other buffer)
        if (s + 1 < NSTEPS) {
            const int jb = jb0 + (s + 1) * JSTEP;
            uint32_t vdst = smb + (((s + 1) & 1) ? VS1_F : VS0_F) * 4;
#pragma unroll
            for (int i = 0; i < 8; i++) {
                int c = tid + 256 * i;
                int row = c >> 5, off = c & 31;
                CP_ASYNC16(smb + KS_F * 4 + row * (132 * 4) + off * 16,
                           (const void*)&g_Kt[(jb + row) * NC + off * 4]);
            }
            CP_COMMIT();
#pragma unroll
            for (int i = 0; i < 8; i++) {
                int c = tid + 256 * i;
                int row = c >> 4, off = c & 15;
                CP_ASYNC16(vdst + row * (68 * 4) + off * 16,
                           (const void*)&g_V[row * NJ + jb + off * 4]);
            }
            CP_COMMIT();
        }

        // ---- GEMM2: warp accumulates O[32n x 64c2] over j=64 ----
#pragma unroll
        for (int k0 = 0; k0 < 64; k0 += 8) {
            uint32_t a[2][4];
#pragma unroll
            for (int mt = 0; mt < 2; mt++) {
                const float* p0 = &Ps[(wm + mt * 16 + g) * 68 + k0 + t];
                const float* p1 = p0 + 8 * 68;
                a[mt][0] = __float_as_uint(p0[0]);
                a[mt][1] = __float_as_uint(p1[0]);
                a[mt][2] = __float_as_uint(p0[4]);
                a[mt][3] = __float_as_uint(p1[4]);
            }
#pragma unroll
            for (int nt = 0; nt < 8; nt++) {
                const float* vp = &Vs[(wn2 + nt * 8 + g) * 68 + k0 + t];
                uint32_t b0 = __float_as_uint(vp[0]);
                uint32_t b1 = __float_as_uint(vp[4]);
#pragma unroll
                for (int mt = 0; mt < 2; mt++)
                    mma8(acc2[mt * 8 + nt], a[mt], b0, b1);
            }
        }
    }

    // ---- epilogue: fragments -> smem [c2][n] -> coalesced partial stores ----
    __syncthreads();
    float* Osm = sm;   // [128][129] floats, reuses Qs region
#pragma unroll
    for (int mt = 0; mt < 2; mt++)
#pragma unroll
        for (int nt = 0; nt < 8; nt++) {
            int n = wm + mt * 16 + g;
            int c2 = wn2 + nt * 8 + 2 * t;
            const float* c = acc2[mt * 8 + nt];
            Osm[c2 * 129 + n]           = c[0];
            Osm[(c2 + 1) * 129 + n]     = c[1];
            Osm[c2 * 129 + n + 8]       = c[2];
            Osm[(c2 + 1) * 129 + n + 8] = c[3];
        }
    __syncthreads();
#pragma unroll
    for (int it = 0; it < 16; it++) {
        int idx = it * 256 + tid;
        int r = idx >> 5, q = idx & 31;
        float4 v = make_float4(Osm[r * 129 + 4 * q], Osm[r * 129 + 4 * q + 1],
                               Osm[r * 129 + 4 * q + 2], Osm[r * 129 + 4 * q + 3]);
        *reinterpret_cast<float4*>(&g_Op[((split << 7) + r) * NN + m0 + 4 * q]) = v;
    }
}

// ---------------------------------------------------------------------------
// Kernel 4: combine partials + residual + S1 -> out [c2][n]
// ---------------------------------------------------------------------------
__global__ void __launch_bounds__(256) reduce_kernel(const float* __restrict__ x,
                                                     float* __restrict__ out) {
    int idx = blockIdx.x * 256 + threadIdx.x;   // float4 units
    int c2 = idx >> 10;
    const float4* x4 = reinterpret_cast<const float4*>(x);
    const float4* o4 = reinterpret_cast<const float4*>(g_Op);
    float4 xv = x4[idx];
    float4 s = make_float4(0.f, 0.f, 0.f, 0.f);
#pragma unroll
    for (int sp = 0; sp < NSPLIT; sp++) {
        float4 v = o4[((sp << 7) + c2) * (NN / 4) + (idx & 1023)];
        s.x += v.x; s.y += v.y; s.z += v.z; s.w += v.w;
    }
    float4 r;
    if (c2 < 64) {
        r.x = xv.x + s.x; r.y = xv.y + s.y; r.z = xv.z + s.z; r.w = xv.w + s.w;
    } else {
        float b = g_S1[c2 - 64];
        r.x = xv.x + b - s.x; r.y = xv.y + b - s.y;
        r.z = xv.z + b - s.z; r.w = xv.w + b - s.w;
    }
    reinterpret_cast<float4*>(out)[idx] = r;
}

// ---------------------------------------------------------------------------
extern "C" void kernel_launch(void* const* d_in, const int* in_sizes, int n_in,
                              void* d_out, int out_size) {
    const float* x  = (const float*)d_in[0];   // [2,64,16,16,16] = [128][4096]
    const float* cw = (const float*)d_in[1];   // [64,64,3]
    const float* cb = (const float*)d_in[2];   // [64]
    float* out = (float*)d_out;

    cudaFuncSetAttribute(conv_kernel, cudaFuncAttributeMaxDynamicSharedMemorySize, CONV_SMEM_BYTES);
    cudaFuncSetAttribute(dspa_main_kernel, cudaFuncAttributeMaxDynamicSharedMemorySize, MAIN_SMEM_BYTES);

    conv_kernel<<<128, 512, CONV_SMEM_BYTES>>>(x, cw, cb);
    s1_kernel<<<64, 256>>>();
    dspa_main_kernel<<<128, 256, MAIN_SMEM_BYTES>>>();
    reduce_kernel<<<512, 256>>>(x, out);
}